// round 4
// baseline (speedup 1.0000x reference)
#include <cuda_runtime.h>
#include <cuda_bf16.h>
#include <math.h>
#include <cstdint>

// Problem constants
#define B_   2
#define T_   2048
#define D_   2048
#define H_   32
#define KVH_ 8
#define HD_  64
#define M_   (B_ * T_)        // 4096 rows (b*T + t)
#define QD_  (H_ * HD_)       // 2048
#define KD_  (KVH_ * HD_)     // 512

// Scratch (device globals — no allocation allowed)
__device__ float g_q[M_ * QD_];
__device__ float g_k[M_ * KD_];
__device__ float g_v[M_ * KD_];
__device__ float g_att[M_ * QD_];

// ---------------------------------------------------------------------------
// Shared GEMM inner machinery: 128x128 block tile, 8-deep K slab, 256 thr,
// 8x8 per-thread microtile, double-buffered SMEM (one barrier per slab).
// ---------------------------------------------------------------------------
struct GemmSmem {
    float AsT[2][8][128];
    float Bs[2][8][128];
};

__device__ __forceinline__ void gemm_body(
    GemmSmem& s, const float* __restrict__ Ap, const float* __restrict__ Bp,
    int K, int N, int tid, float acc[8][8])
{
    const int arow = tid >> 1;          // 0..127
    const int akc  = (tid & 1) * 4;     // 0 or 4
    const int brow = tid >> 5;          // 0..7
    const int bnc  = (tid & 31) * 4;    // 0..124
    const int ty   = tid >> 4;
    const int tx   = tid & 15;

    // Prologue: slab 0 into buffer 0
    {
        const float4 av = *(const float4*)(Ap + (size_t)arow * K + akc);
        const float4 bv = *(const float4*)(Bp + (size_t)brow * N + bnc);
        s.AsT[0][akc + 0][arow] = av.x;
        s.AsT[0][akc + 1][arow] = av.y;
        s.AsT[0][akc + 2][arow] = av.z;
        s.AsT[0][akc + 3][arow] = av.w;
        *(float4*)&s.Bs[0][brow][bnc] = bv;
    }
    __syncthreads();

    int buf = 0;
    for (int k0 = 0; k0 < K; k0 += 8) {
        const bool more = (k0 + 8 < K);
        float4 av, bv;
        if (more) {
            av = *(const float4*)(Ap + (size_t)arow * K + (k0 + 8) + akc);
            bv = *(const float4*)(Bp + (size_t)(k0 + 8 + brow) * N + bnc);
        }

#pragma unroll
        for (int kk = 0; kk < 8; kk++) {
            float a[8], b[8];
            *(float4*)(a)     = *(const float4*)&s.AsT[buf][kk][ty * 8];
            *(float4*)(a + 4) = *(const float4*)&s.AsT[buf][kk][ty * 8 + 4];
            *(float4*)(b)     = *(const float4*)&s.Bs[buf][kk][tx * 8];
            *(float4*)(b + 4) = *(const float4*)&s.Bs[buf][kk][tx * 8 + 4];
#pragma unroll
            for (int i = 0; i < 8; i++)
#pragma unroll
                for (int j = 0; j < 8; j++)
                    acc[i][j] = fmaf(a[i], b[j], acc[i][j]);
        }

        if (more) {
            const int nb = buf ^ 1;
            s.AsT[nb][akc + 0][arow] = av.x;
            s.AsT[nb][akc + 1][arow] = av.y;
            s.AsT[nb][akc + 2][arow] = av.z;
            s.AsT[nb][akc + 3][arow] = av.w;
            *(float4*)&s.Bs[nb][brow][bnc] = bv;
            __syncthreads();
            buf = nb;
        }
    }
}

__device__ __forceinline__ void gemm_store(
    float* __restrict__ C, int N, int mBase, int nBase, int tid, float acc[8][8])
{
    const int ty = tid >> 4;
    const int tx = tid & 15;
#pragma unroll
    for (int i = 0; i < 8; i++) {
        float* Cp = C + (size_t)(mBase + ty * 8 + i) * N + nBase + tx * 8;
        *(float4*)Cp       = make_float4(acc[i][0], acc[i][1], acc[i][2], acc[i][3]);
        *(float4*)(Cp + 4) = make_float4(acc[i][4], acc[i][5], acc[i][6], acc[i][7]);
    }
}

// Generic SGEMM (used for output projection)
__global__ __launch_bounds__(256, 2)
void sgemm128(const float* __restrict__ A, const float* __restrict__ Bm,
              float* __restrict__ C, int M, int N, int K) {
    __shared__ GemmSmem s;
    const int tid = threadIdx.x;
    const int mBase = blockIdx.y * 128;
    const int nBase = blockIdx.x * 128;

    float acc[8][8];
#pragma unroll
    for (int i = 0; i < 8; i++)
#pragma unroll
        for (int j = 0; j < 8; j++) acc[i][j] = 0.f;

    gemm_body(s, A + (size_t)mBase * K, Bm + nBase, K, N, tid, acc);
    gemm_store(C, N, mBase, nBase, tid, acc);
}

// Fused QKV projection: blockIdx.x in [0,24).
//   [0,16)  -> wq col-block -> g_q (N=2048)
//   [16,20) -> wk col-block -> g_k (N=512)
//   [20,24) -> wv col-block -> g_v (N=512)
__global__ __launch_bounds__(256, 2)
void qkv_gemm(const float* __restrict__ x,
              const float* __restrict__ wq, const float* __restrict__ wk,
              const float* __restrict__ wv,
              float* __restrict__ pq, float* __restrict__ pk, float* __restrict__ pv) {
    __shared__ GemmSmem s;
    const int tid = threadIdx.x;
    const int mBase = blockIdx.y * 128;
    const int bx = blockIdx.x;

    const float* W;
    float* C;
    int N, nBase;
    if (bx < 16)      { W = wq; C = pq; N = QD_; nBase = bx * 128; }
    else if (bx < 20) { W = wk; C = pk; N = KD_; nBase = (bx - 16) * 128; }
    else              { W = wv; C = pv; N = KD_; nBase = (bx - 20) * 128; }

    float acc[8][8];
#pragma unroll
    for (int i = 0; i < 8; i++)
#pragma unroll
        for (int j = 0; j < 8; j++) acc[i][j] = 0.f;

    gemm_body(s, x + (size_t)mBase * D_, W + nBase, D_, N, tid, acc);
    gemm_store(C, N, mBase, nBase, tid, acc);
}

// ---------------------------------------------------------------------------
// RoPE in place on [M, heads*64]: pair (d, d+32) per thread.
// ---------------------------------------------------------------------------
__global__ void rope_kernel(float* __restrict__ t, const float* __restrict__ cosT,
                            const float* __restrict__ sinT, int heads) {
    const int idx = blockIdx.x * blockDim.x + threadIdx.x;
    const int total = M_ * heads * (HD_ / 2);
    if (idx >= total) return;
    const int d = idx & 31;
    const int h = (idx >> 5) % heads;
    const int m = idx / (heads * 32);
    const int tt = m & (T_ - 1);   // m % T
    const float c = cosT[tt * 32 + d];
    const float s = sinT[tt * 32 + d];
    float* p = t + (size_t)m * heads * HD_ + h * HD_ + d;
    const float q1 = p[0], q2 = p[32];
    p[0]  = fmaf(q1, c, -q2 * s);
    p[32] = fmaf(q2, c,  q1 * s);
}

// ---------------------------------------------------------------------------
// Causal GQA flash attention, fp32.
// Grid: (T/64, H, B). Block: 256 threads (16x16). BM = BN = 64, HD = 64.
// Online softmax; causal tile skipping (only j0 <= i0 tiles visited).
// ---------------------------------------------------------------------------
#define LDP 68   // padded leading dim for 64-wide shared tiles

__global__ __launch_bounds__(256, 2)
void attn_kernel(float* __restrict__ o) {
    extern __shared__ float sm[];
    float* QsT = sm;                 // [64][LDP]  QsT[d][row]
    float* KsT = QsT + 64 * LDP;     // [64][LDP]  KsT[d][col]
    float* Vs  = KsT + 64 * LDP;     // [64][LDP]  Vs[key][d]
    float* Ss  = Vs  + 64 * LDP;     // [64][LDP]  Ss[row][col] (scores, then P)
    float* m_s = Ss  + 64 * LDP;     // [64] running max
    float* l_s = m_s + 64;           // [64] running sum
    float* a_s = l_s + 64;           // [64] rescale alpha

    const int i0  = blockIdx.x * 64;
    const int h   = blockIdx.y;
    const int b   = blockIdx.z;
    const int kvh = h >> 2;          // N_REP = 4
    const int tid = threadIdx.x;
    const int tx  = tid & 15;
    const int ty  = tid >> 4;

    // Load Q tile, transposed into QsT[d][row]
#pragma unroll
    for (int it = 0; it < 4; it++) {
        const int idx = tid + it * 256;       // float4 index within 64x64 tile
        const int row = idx >> 4;
        const int d4  = (idx & 15) * 4;
        const float4 qv = *(const float4*)(g_q + (size_t)(b * T_ + i0 + row) * QD_ + h * HD_ + d4);
        QsT[(d4 + 0) * LDP + row] = qv.x;
        QsT[(d4 + 1) * LDP + row] = qv.y;
        QsT[(d4 + 2) * LDP + row] = qv.z;
        QsT[(d4 + 3) * LDP + row] = qv.w;
    }
    if (tid < 64) { m_s[tid] = -INFINITY; l_s[tid] = 0.f; }

    float O[4][4];
#pragma unroll
    for (int i = 0; i < 4; i++)
#pragma unroll
        for (int j = 0; j < 4; j++) O[i][j] = 0.f;

    const float scale = 0.125f;  // 1/sqrt(64)

    for (int j0 = 0; j0 <= i0; j0 += 64) {
        __syncthreads();   // previous tile fully consumed before overwrite
        // Load K (transposed) and V tiles
#pragma unroll
        for (int it = 0; it < 4; it++) {
            const int idx = tid + it * 256;
            const int row = idx >> 4;
            const int d4  = (idx & 15) * 4;
            const size_t gofs = (size_t)(b * T_ + j0 + row) * KD_ + kvh * HD_ + d4;
            const float4 kv = *(const float4*)(g_k + gofs);
            KsT[(d4 + 0) * LDP + row] = kv.x;
            KsT[(d4 + 1) * LDP + row] = kv.y;
            KsT[(d4 + 2) * LDP + row] = kv.z;
            KsT[(d4 + 3) * LDP + row] = kv.w;
            *(float4*)&Vs[row * LDP + d4] = *(const float4*)(g_v + gofs);
        }
        __syncthreads();

        // S = scale * Q @ K^T  (4x4 per thread)
        float acc[4][4];
#pragma unroll
        for (int i = 0; i < 4; i++)
#pragma unroll
            for (int j = 0; j < 4; j++) acc[i][j] = 0.f;
#pragma unroll 8
        for (int d = 0; d < 64; d++) {
            const float4 qa = *(const float4*)&QsT[d * LDP + ty * 4];
            const float4 kb = *(const float4*)&KsT[d * LDP + tx * 4];
            const float a4[4] = {qa.x, qa.y, qa.z, qa.w};
            const float b4[4] = {kb.x, kb.y, kb.z, kb.w};
#pragma unroll
            for (int i = 0; i < 4; i++)
#pragma unroll
                for (int j = 0; j < 4; j++)
                    acc[i][j] = fmaf(a4[i], b4[j], acc[i][j]);
        }
        const bool diag = (j0 == i0);
#pragma unroll
        for (int i = 0; i < 4; i++) {
            const int row = ty * 4 + i;
            float sv[4];
#pragma unroll
            for (int j = 0; j < 4; j++) {
                float s = acc[i][j] * scale;
                if (diag && (tx * 4 + j > row)) s = -1e30f;
                sv[j] = s;
            }
            *(float4*)&Ss[row * LDP + tx * 4] = make_float4(sv[0], sv[1], sv[2], sv[3]);
        }
        __syncthreads();

        // Online softmax: 4 threads per row, 16 cols each
        {
            const int row  = tid >> 2;
            const int base = (tid & 3) * 16;
            const float mo = m_s[row];
            float v[16];
            float mt = -INFINITY;
#pragma unroll
            for (int jj = 0; jj < 16; jj++) {
                v[jj] = Ss[row * LDP + base + jj];
                mt = fmaxf(mt, v[jj]);
            }
            mt = fmaxf(mt, __shfl_xor_sync(0xffffffffu, mt, 1));
            mt = fmaxf(mt, __shfl_xor_sync(0xffffffffu, mt, 2));
            const float mn = fmaxf(mo, mt);
            const float alpha = __expf(mo - mn);  // 0 on first tile (mo = -inf)
            float sum = 0.f;
#pragma unroll
            for (int jj = 0; jj < 16; jj++) {
                const float p = __expf(v[jj] - mn);
                Ss[row * LDP + base + jj] = p;
                sum += p;
            }
            sum += __shfl_xor_sync(0xffffffffu, sum, 1);
            sum += __shfl_xor_sync(0xffffffffu, sum, 2);
            __syncwarp();
            if ((tid & 3) == 0) {
                l_s[row] = l_s[row] * alpha + sum;
                m_s[row] = mn;
                a_s[row] = alpha;
            }
        }
        __syncthreads();

        // Rescale O, then O += P @ V
        float alr[4];
#pragma unroll
        for (int i = 0; i < 4; i++) alr[i] = a_s[ty * 4 + i];
#pragma unroll
        for (int i = 0; i < 4; i++)
#pragma unroll
            for (int j = 0; j < 4; j++) O[i][j] *= alr[i];

#pragma unroll 8
        for (int kk = 0; kk < 64; kk++) {
            const float4 vv = *(const float4*)&Vs[kk * LDP + tx * 4];
            const float vb[4] = {vv.x, vv.y, vv.z, vv.w};
            float pr[4];
#pragma unroll
            for (int i = 0; i < 4; i++) pr[i] = Ss[(ty * 4 + i) * LDP + kk];
#pragma unroll
            for (int i = 0; i < 4; i++)
#pragma unroll
                for (int j = 0; j < 4; j++)
                    O[i][j] = fmaf(pr[i], vb[j], O[i][j]);
        }
    }

    // Epilogue: divide by l and store (l_s finalized before last tile's sync)
    float linv[4];
#pragma unroll
    for (int i = 0; i < 4; i++) linv[i] = 1.0f / l_s[ty * 4 + i];
#pragma unroll
    for (int i = 0; i < 4; i++) {
        float* op = o + (size_t)(b * T_ + i0 + ty * 4 + i) * QD_ + h * HD_ + tx * 4;
        *(float4*)op = make_float4(O[i][0] * linv[i], O[i][1] * linv[i],
                                   O[i][2] * linv[i], O[i][3] * linv[i]);
    }
}

// ---------------------------------------------------------------------------
// Launch
// ---------------------------------------------------------------------------
extern "C" void kernel_launch(void* const* d_in, const int* in_sizes, int n_in,
                              void* d_out, int out_size) {
    const float* x    = (const float*)d_in[0];
    const float* cosT = (const float*)d_in[1];
    const float* sinT = (const float*)d_in[2];
    const float* wq   = (const float*)d_in[3];
    const float* wk   = (const float*)d_in[4];
    const float* wv   = (const float*)d_in[5];
    const float* wo   = (const float*)d_in[6];
    float* out        = (float*)d_out;

    float *pq, *pk, *pv, *pa;
    cudaGetSymbolAddress((void**)&pq, g_q);
    cudaGetSymbolAddress((void**)&pk, g_k);
    cudaGetSymbolAddress((void**)&pv, g_v);
    cudaGetSymbolAddress((void**)&pa, g_att);

    // Fused QKV projections: 16 Q col-blocks + 4 K + 4 V = 24
    qkv_gemm<<<dim3(24, M_ / 128), 256>>>(x, wq, wk, wv, pq, pk, pv);

    // RoPE on Q and K
    {
        const int tq = M_ * H_ * (HD_ / 2);
        rope_kernel<<<(tq + 255) / 256, 256>>>(pq, cosT, sinT, H_);
        const int tk = M_ * KVH_ * (HD_ / 2);
        rope_kernel<<<(tk + 255) / 256, 256>>>(pk, cosT, sinT, KVH_);
    }

    // Attention
    {
        const int smem = (4 * 64 * LDP + 3 * 64) * (int)sizeof(float);
        cudaFuncSetAttribute(attn_kernel, cudaFuncAttributeMaxDynamicSharedMemorySize, smem);
        attn_kernel<<<dim3(T_ / 64, H_, B_), 256, smem>>>(pa);
    }

    // Output projection
    sgemm128<<<dim3(D_ / 128, M_ / 128), 256>>>(pa, wo, out, M_, D_, D_);
}

// round 7
// speedup vs baseline: 1.8747x; 1.8747x over previous
#include <cuda_runtime.h>
#include <cuda_bf16.h>
#include <math.h>
#include <cstdint>

// Problem constants
#define B_   2
#define T_   2048
#define D_   2048
#define H_   32
#define KVH_ 8
#define HD_  64
#define M_   (B_ * T_)        // 4096 rows (b*T + t)
#define QD_  (H_ * HD_)       // 2048
#define KD_  (KVH_ * HD_)     // 512

// Scratch (device globals — no allocation allowed)
__device__ float g_q[M_ * QD_];
__device__ float g_k[M_ * KD_];
__device__ float g_v[M_ * KD_];
__device__ float g_att[M_ * QD_];

// ===========================================================================
// TF32 tensor-core GEMM: C[M,N] = A[M,K] @ B[K,N], row-major.
// BM=128, BN=128, BK=32. 256 threads = 8 warps in 2(m) x 4(n); warp tile 64x32.
// mma.sync.aligned.m16n8k8.row.col.f32.tf32.tf32.f32, fp32 accumulate.
// Double-buffered SMEM, cvt.rna.tf32 at staging.
// ===========================================================================
#define LDA 36
#define LDB 136
#define ASZ (128 * LDA)          // floats per A buffer
#define BSZ (32 * LDB)           // floats per B buffer
#define TG_SMEM_BYTES ((2 * ASZ + 2 * BSZ) * 4)   // 71680 B

__device__ __forceinline__ uint32_t f2tf32(float f) {
    uint32_t u;
    asm("cvt.rna.tf32.f32 %0, %1;" : "=r"(u) : "f"(f));
    return u;
}
__device__ __forceinline__ float tf32f(float f) { return __uint_as_float(f2tf32(f)); }

__device__ __forceinline__ void mma_tf32(float c[4],
                                         uint32_t a0, uint32_t a1, uint32_t a2, uint32_t a3,
                                         uint32_t b0, uint32_t b1) {
    asm volatile(
        "mma.sync.aligned.m16n8k8.row.col.f32.tf32.tf32.f32 "
        "{%0,%1,%2,%3},{%4,%5,%6,%7},{%8,%9},{%0,%1,%2,%3};"
        : "+f"(c[0]), "+f"(c[1]), "+f"(c[2]), "+f"(c[3])
        : "r"(a0), "r"(a1), "r"(a2), "r"(a3), "r"(b0), "r"(b1));
}

// Core body. Ap = A + mBase*K, Bp = B + nBase, Cp = C + mBase*N + nBase.
__device__ __forceinline__ void tgemm_body(
    float* __restrict__ As, float* __restrict__ Bs,
    const float* __restrict__ Ap, const float* __restrict__ Bp,
    float* __restrict__ Cp, int N, int K, int tid)
{
    const int warp = tid >> 5, lane = tid & 31;
    const int gid = lane >> 2, ctid = lane & 3;
    const int wm = (warp & 1) * 64;
    const int wn = (warp >> 1) * 32;

    // staging indices
    const int arow = tid >> 3;            // 0..31, rows arow + 32*i
    const int ac4  = (tid & 7) * 4;       // 0..28
    const int brow = tid >> 5;            // 0..7, rows brow + 8*i
    const int bc4  = (tid & 31) * 4;      // 0..124

    float acc[4][4][4];
#pragma unroll
    for (int mi = 0; mi < 4; mi++)
#pragma unroll
        for (int ni = 0; ni < 4; ni++)
#pragma unroll
            for (int r = 0; r < 4; r++) acc[mi][ni][r] = 0.f;

    float4 apf[4], bpf[4];
    // Prologue: load slab 0
#pragma unroll
    for (int i = 0; i < 4; i++)
        apf[i] = *(const float4*)(Ap + (size_t)(arow + 32 * i) * K + ac4);
#pragma unroll
    for (int i = 0; i < 4; i++)
        bpf[i] = *(const float4*)(Bp + (size_t)(brow + 8 * i) * N + bc4);
    // stage into buffer 0 (cvt to tf32)
#pragma unroll
    for (int i = 0; i < 4; i++) {
        *(float4*)(As + (size_t)(arow + 32 * i) * LDA + ac4) =
            make_float4(tf32f(apf[i].x), tf32f(apf[i].y), tf32f(apf[i].z), tf32f(apf[i].w));
        *(float4*)(Bs + (size_t)(brow + 8 * i) * LDB + bc4) =
            make_float4(tf32f(bpf[i].x), tf32f(bpf[i].y), tf32f(bpf[i].z), tf32f(bpf[i].w));
    }
    __syncthreads();

    int buf = 0;
    for (int k0 = 0; k0 < K; k0 += 32) {
        const bool more = (k0 + 32 < K);
        if (more) {
#pragma unroll
            for (int i = 0; i < 4; i++)
                apf[i] = *(const float4*)(Ap + (size_t)(arow + 32 * i) * K + (k0 + 32) + ac4);
#pragma unroll
            for (int i = 0; i < 4; i++)
                bpf[i] = *(const float4*)(Bp + (size_t)(brow + 8 * i + k0 + 32) * N + bc4);
        }

        const float* Ab = As + buf * ASZ;
        const float* Bb = Bs + buf * BSZ;
#pragma unroll
        for (int ks = 0; ks < 4; ks++) {
            const int kb = ks * 8;
            uint32_t af[4][4], bf[4][2];
#pragma unroll
            for (int mi = 0; mi < 4; mi++) {
                const float* ap = Ab + (size_t)(wm + mi * 16 + gid) * LDA + kb + ctid;
                af[mi][0] = __float_as_uint(ap[0]);
                af[mi][1] = __float_as_uint(ap[8 * LDA]);
                af[mi][2] = __float_as_uint(ap[4]);
                af[mi][3] = __float_as_uint(ap[8 * LDA + 4]);
            }
#pragma unroll
            for (int ni = 0; ni < 4; ni++) {
                const float* bp = Bb + (size_t)(kb + ctid) * LDB + wn + ni * 8 + gid;
                bf[ni][0] = __float_as_uint(bp[0]);
                bf[ni][1] = __float_as_uint(bp[4 * LDB]);
            }
#pragma unroll
            for (int mi = 0; mi < 4; mi++)
#pragma unroll
                for (int ni = 0; ni < 4; ni++)
                    mma_tf32(acc[mi][ni], af[mi][0], af[mi][1], af[mi][2], af[mi][3],
                             bf[ni][0], bf[ni][1]);
        }

        if (more) {
            const int nb = buf ^ 1;
            float* An = As + nb * ASZ;
            float* Bn = Bs + nb * BSZ;
#pragma unroll
            for (int i = 0; i < 4; i++) {
                *(float4*)(An + (size_t)(arow + 32 * i) * LDA + ac4) =
                    make_float4(tf32f(apf[i].x), tf32f(apf[i].y), tf32f(apf[i].z), tf32f(apf[i].w));
                *(float4*)(Bn + (size_t)(brow + 8 * i) * LDB + bc4) =
                    make_float4(tf32f(bpf[i].x), tf32f(bpf[i].y), tf32f(bpf[i].z), tf32f(bpf[i].w));
            }
            __syncthreads();
            buf = nb;
        }
    }

    // Epilogue: c0/c1 at (gid, 2*ctid[+1]), c2/c3 at (gid+8, ...)
#pragma unroll
    for (int mi = 0; mi < 4; mi++) {
#pragma unroll
        for (int ni = 0; ni < 4; ni++) {
            const int r0 = wm + mi * 16 + gid;
            const int cc = wn + ni * 8 + ctid * 2;
            *(float2*)(Cp + (size_t)r0 * N + cc)       = make_float2(acc[mi][ni][0], acc[mi][ni][1]);
            *(float2*)(Cp + (size_t)(r0 + 8) * N + cc) = make_float2(acc[mi][ni][2], acc[mi][ni][3]);
        }
    }
}

// Generic tf32 GEMM (output projection)
__global__ __launch_bounds__(256)
void tgemm(const float* __restrict__ A, const float* __restrict__ Bm,
           float* __restrict__ C, int M, int N, int K) {
    extern __shared__ float smf[];
    float* As = smf;
    float* Bs = smf + 2 * ASZ;
    const int mBase = blockIdx.y * 128;
    const int nBase = blockIdx.x * 128;
    tgemm_body(As, Bs, A + (size_t)mBase * K, Bm + nBase,
               C + (size_t)mBase * N + nBase, N, K, threadIdx.x);
}

// Fused QKV projection: blockIdx.x in [0,24):
//   [0,16) -> wq -> g_q (N=2048); [16,20) -> wk -> g_k; [20,24) -> wv -> g_v
__global__ __launch_bounds__(256)
void qkv_tgemm(const float* __restrict__ x,
               const float* __restrict__ wq, const float* __restrict__ wk,
               const float* __restrict__ wv,
               float* __restrict__ pq, float* __restrict__ pk, float* __restrict__ pv) {
    extern __shared__ float smf[];
    float* As = smf;
    float* Bs = smf + 2 * ASZ;
    const int mBase = blockIdx.y * 128;
    const int bx = blockIdx.x;

    const float* W; float* C; int N, nBase;
    if (bx < 16)      { W = wq; C = pq; N = QD_; nBase = bx * 128; }
    else if (bx < 20) { W = wk; C = pk; N = KD_; nBase = (bx - 16) * 128; }
    else              { W = wv; C = pv; N = KD_; nBase = (bx - 20) * 128; }

    tgemm_body(As, Bs, x + (size_t)mBase * D_, W + nBase,
               C + (size_t)mBase * N + nBase, N, D_, threadIdx.x);
}

// ---------------------------------------------------------------------------
// RoPE in place on [M, heads*64]: pair (d, d+32) per thread.
// ---------------------------------------------------------------------------
__global__ void rope_kernel(float* __restrict__ t, const float* __restrict__ cosT,
                            const float* __restrict__ sinT, int heads) {
    const int idx = blockIdx.x * blockDim.x + threadIdx.x;
    const int total = M_ * heads * (HD_ / 2);
    if (idx >= total) return;
    const int d = idx & 31;
    const int h = (idx >> 5) % heads;
    const int m = idx / (heads * 32);
    const int tt = m & (T_ - 1);   // m % T
    const float c = cosT[tt * 32 + d];
    const float s = sinT[tt * 32 + d];
    float* p = t + (size_t)m * heads * HD_ + h * HD_ + d;
    const float q1 = p[0], q2 = p[32];
    p[0]  = fmaf(q1, c, -q2 * s);
    p[32] = fmaf(q2, c,  q1 * s);
}

// ---------------------------------------------------------------------------
// Causal GQA flash attention, fp32.
// Grid: (T/64, H, B). Block: 256 threads (16x16). BM = BN = 64, HD = 64.
// P stored TRANSPOSED (Ps[col][row]) by softmax so the PV loop is two
// vectorized LDS.128 per kk (one broadcast) instead of 1 + 4 scalars.
// ---------------------------------------------------------------------------
#define LDP 68   // padded leading dim for 64-wide shared tiles

__global__ __launch_bounds__(256, 2)
void attn_kernel(float* __restrict__ o) {
    extern __shared__ float sm[];
    float* QsT = sm;                 // [64][LDP]  QsT[d][row]
    float* KsT = QsT + 64 * LDP;     // [64][LDP]  KsT[d][col]
    float* Vs  = KsT + 64 * LDP;     // [64][LDP]  Vs[key][d]
    float* Ss  = Vs  + 64 * LDP;     // [64][LDP]  Ss[row][col] (raw scores)
    float* Ps  = Ss  + 64 * LDP;     // [64][LDP]  Ps[col][row] (P transposed)
    float* m_s = Ps  + 64 * LDP;     // [64] running max
    float* l_s = m_s + 64;           // [64] running sum
    float* a_s = l_s + 64;           // [64] rescale alpha

    const int i0  = blockIdx.x * 64;
    const int h   = blockIdx.y;
    const int b   = blockIdx.z;
    const int kvh = h >> 2;          // N_REP = 4
    const int tid = threadIdx.x;
    const int tx  = tid & 15;
    const int ty  = tid >> 4;

    // Load Q tile, transposed into QsT[d][row]
#pragma unroll
    for (int it = 0; it < 4; it++) {
        const int idx = tid + it * 256;       // float4 index within 64x64 tile
        const int row = idx >> 4;
        const int d4  = (idx & 15) * 4;
        const float4 qv = *(const float4*)(g_q + (size_t)(b * T_ + i0 + row) * QD_ + h * HD_ + d4);
        QsT[(d4 + 0) * LDP + row] = qv.x;
        QsT[(d4 + 1) * LDP + row] = qv.y;
        QsT[(d4 + 2) * LDP + row] = qv.z;
        QsT[(d4 + 3) * LDP + row] = qv.w;
    }
    if (tid < 64) { m_s[tid] = -INFINITY; l_s[tid] = 0.f; }

    float O[4][4];
#pragma unroll
    for (int i = 0; i < 4; i++)
#pragma unroll
        for (int j = 0; j < 4; j++) O[i][j] = 0.f;

    const float scale = 0.125f;  // 1/sqrt(64)

    for (int j0 = 0; j0 <= i0; j0 += 64) {
        __syncthreads();   // previous tile fully consumed before overwrite
        // Load K (transposed) and V tiles
#pragma unroll
        for (int it = 0; it < 4; it++) {
            const int idx = tid + it * 256;
            const int row = idx >> 4;
            const int d4  = (idx & 15) * 4;
            const size_t gofs = (size_t)(b * T_ + j0 + row) * KD_ + kvh * HD_ + d4;
            const float4 kv = *(const float4*)(g_k + gofs);
            KsT[(d4 + 0) * LDP + row] = kv.x;
            KsT[(d4 + 1) * LDP + row] = kv.y;
            KsT[(d4 + 2) * LDP + row] = kv.z;
            KsT[(d4 + 3) * LDP + row] = kv.w;
            *(float4*)&Vs[row * LDP + d4] = *(const float4*)(g_v + gofs);
        }
        __syncthreads();

        // S = scale * Q @ K^T  (4x4 per thread)
        float acc[4][4];
#pragma unroll
        for (int i = 0; i < 4; i++)
#pragma unroll
            for (int j = 0; j < 4; j++) acc[i][j] = 0.f;
#pragma unroll 8
        for (int d = 0; d < 64; d++) {
            const float4 qa = *(const float4*)&QsT[d * LDP + ty * 4];
            const float4 kb = *(const float4*)&KsT[d * LDP + tx * 4];
            const float a4[4] = {qa.x, qa.y, qa.z, qa.w};
            const float b4[4] = {kb.x, kb.y, kb.z, kb.w};
#pragma unroll
            for (int i = 0; i < 4; i++)
#pragma unroll
                for (int j = 0; j < 4; j++)
                    acc[i][j] = fmaf(a4[i], b4[j], acc[i][j]);
        }
        const bool diag = (j0 == i0);
#pragma unroll
        for (int i = 0; i < 4; i++) {
            const int row = ty * 4 + i;
            float sv[4];
#pragma unroll
            for (int j = 0; j < 4; j++) {
                float s = acc[i][j] * scale;
                if (diag && (tx * 4 + j > row)) s = -1e30f;
                sv[j] = s;
            }
            *(float4*)&Ss[row * LDP + tx * 4] = make_float4(sv[0], sv[1], sv[2], sv[3]);
        }
        __syncthreads();

        // Online softmax: 4 threads per row, 16 cols each.
        // Reads Ss[row][col]; writes P TRANSPOSED into Ps[col][row].
        {
            const int row  = tid >> 2;
            const int base = (tid & 3) * 16;
            const float mo = m_s[row];
            float v[16];
            float mt = -INFINITY;
#pragma unroll
            for (int jj = 0; jj < 16; jj++) {
                v[jj] = Ss[row * LDP + base + jj];
                mt = fmaxf(mt, v[jj]);
            }
            mt = fmaxf(mt, __shfl_xor_sync(0xffffffffu, mt, 1));
            mt = fmaxf(mt, __shfl_xor_sync(0xffffffffu, mt, 2));
            const float mn = fmaxf(mo, mt);
            const float alpha = __expf(mo - mn);  // 0 on first tile (mo = -inf)
            float sum = 0.f;
#pragma unroll
            for (int jj = 0; jj < 16; jj++) {
                const float p = __expf(v[jj] - mn);
                Ps[(base + jj) * LDP + row] = p;
                sum += p;
            }
            sum += __shfl_xor_sync(0xffffffffu, sum, 1);
            sum += __shfl_xor_sync(0xffffffffu, sum, 2);
            __syncwarp();
            if ((tid & 3) == 0) {
                l_s[row] = l_s[row] * alpha + sum;
                m_s[row] = mn;
                a_s[row] = alpha;
            }
        }
        __syncthreads();

        // Rescale O, then O += P @ V (both operands vectorized from SMEM)
        float alr[4];
#pragma unroll
        for (int i = 0; i < 4; i++) alr[i] = a_s[ty * 4 + i];
#pragma unroll
        for (int i = 0; i < 4; i++)
#pragma unroll
            for (int j = 0; j < 4; j++) O[i][j] *= alr[i];

#pragma unroll 8
        for (int kk = 0; kk < 64; kk++) {
            const float4 vv = *(const float4*)&Vs[kk * LDP + tx * 4];
            const float4 pp = *(const float4*)&Ps[kk * LDP + ty * 4];  // broadcast
            const float vb[4] = {vv.x, vv.y, vv.z, vv.w};
            const float pr[4] = {pp.x, pp.y, pp.z, pp.w};
#pragma unroll
            for (int i = 0; i < 4; i++)
#pragma unroll
                for (int j = 0; j < 4; j++)
                    O[i][j] = fmaf(pr[i], vb[j], O[i][j]);
        }
    }

    // Epilogue: divide by l and store
    float linv[4];
#pragma unroll
    for (int i = 0; i < 4; i++) linv[i] = 1.0f / l_s[ty * 4 + i];
#pragma unroll
    for (int i = 0; i < 4; i++) {
        float* op = o + (size_t)(b * T_ + i0 + ty * 4 + i) * QD_ + h * HD_ + tx * 4;
        *(float4*)op = make_float4(O[i][0] * linv[i], O[i][1] * linv[i],
                                   O[i][2] * linv[i], O[i][3] * linv[i]);
    }
}

// ---------------------------------------------------------------------------
// Launch
// ---------------------------------------------------------------------------
extern "C" void kernel_launch(void* const* d_in, const int* in_sizes, int n_in,
                              void* d_out, int out_size) {
    const float* x    = (const float*)d_in[0];
    const float* cosT = (const float*)d_in[1];
    const float* sinT = (const float*)d_in[2];
    const float* wq   = (const float*)d_in[3];
    const float* wk   = (const float*)d_in[4];
    const float* wv   = (const float*)d_in[5];
    const float* wo   = (const float*)d_in[6];
    float* out        = (float*)d_out;

    float *pq, *pk, *pv, *pa;
    cudaGetSymbolAddress((void**)&pq, g_q);
    cudaGetSymbolAddress((void**)&pk, g_k);
    cudaGetSymbolAddress((void**)&pv, g_v);
    cudaGetSymbolAddress((void**)&pa, g_att);

    cudaFuncSetAttribute(qkv_tgemm, cudaFuncAttributeMaxDynamicSharedMemorySize, TG_SMEM_BYTES);
    cudaFuncSetAttribute(tgemm, cudaFuncAttributeMaxDynamicSharedMemorySize, TG_SMEM_BYTES);

    // Fused QKV projections (tf32 tensor cores): 16 Q + 4 K + 4 V col-blocks
    qkv_tgemm<<<dim3(24, M_ / 128), 256, TG_SMEM_BYTES>>>(x, wq, wk, wv, pq, pk, pv);

    // RoPE on Q and K
    {
        const int tq = M_ * H_ * (HD_ / 2);
        rope_kernel<<<(tq + 255) / 256, 256>>>(pq, cosT, sinT, H_);
        const int tk = M_ * KVH_ * (HD_ / 2);
        rope_kernel<<<(tk + 255) / 256, 256>>>(pk, cosT, sinT, KVH_);
    }

    // Attention (fp32)
    {
        const int smem = (5 * 64 * LDP + 3 * 64) * (int)sizeof(float);
        cudaFuncSetAttribute(attn_kernel, cudaFuncAttributeMaxDynamicSharedMemorySize, smem);
        attn_kernel<<<dim3(T_ / 64, H_, B_), 256, smem>>>(pa);
    }

    // Output projection (tf32 tensor cores)
    tgemm<<<dim3(D_ / 128, M_ / 128), 256, TG_SMEM_BYTES>>>(pa, wo, out, M_, D_, D_);
}

// round 9
// speedup vs baseline: 3.3278x; 1.7751x over previous
#include <cuda_runtime.h>
#include <cuda_bf16.h>
#include <math.h>
#include <cstdint>

// Problem constants
#define B_   2
#define T_   2048
#define D_   2048
#define H_   32
#define KVH_ 8
#define HD_  64
#define M_   (B_ * T_)        // 4096 rows (b*T + t)
#define QD_  (H_ * HD_)       // 2048
#define KD_  (KVH_ * HD_)     // 512

// Scratch (device globals — no allocation allowed)
__device__ float g_q[M_ * QD_];
__device__ float g_k[M_ * KD_];
__device__ float g_v[M_ * KD_];
__device__ float g_att[M_ * QD_];

// ===========================================================================
// TF32 tensor-core GEMM (validated round 7): C[M,N] = A[M,K] @ B[K,N].
// BM=128, BN=128, BK=32. 256 threads = 8 warps in 2(m) x 4(n); warp tile 64x32.
// ===========================================================================
#define LDA 36
#define LDB 136
#define ASZ (128 * LDA)
#define BSZ (32 * LDB)
#define TG_SMEM_BYTES ((2 * ASZ + 2 * BSZ) * 4)   // 71680 B

__device__ __forceinline__ uint32_t f2tf32(float f) {
    uint32_t u;
    asm("cvt.rna.tf32.f32 %0, %1;" : "=r"(u) : "f"(f));
    return u;
}
__device__ __forceinline__ float tf32f(float f) { return __uint_as_float(f2tf32(f)); }

__device__ __forceinline__ void mma_tf32(float c[4],
                                         uint32_t a0, uint32_t a1, uint32_t a2, uint32_t a3,
                                         uint32_t b0, uint32_t b1) {
    asm volatile(
        "mma.sync.aligned.m16n8k8.row.col.f32.tf32.tf32.f32 "
        "{%0,%1,%2,%3},{%4,%5,%6,%7},{%8,%9},{%0,%1,%2,%3};"
        : "+f"(c[0]), "+f"(c[1]), "+f"(c[2]), "+f"(c[3])
        : "r"(a0), "r"(a1), "r"(a2), "r"(a3), "r"(b0), "r"(b1));
}

__device__ __forceinline__ void tgemm_body(
    float* __restrict__ As, float* __restrict__ Bs,
    const float* __restrict__ Ap, const float* __restrict__ Bp,
    float* __restrict__ Cp, int N, int K, int tid)
{
    const int warp = tid >> 5, lane = tid & 31;
    const int gid = lane >> 2, ctid = lane & 3;
    const int wm = (warp & 1) * 64;
    const int wn = (warp >> 1) * 32;

    const int arow = tid >> 3;
    const int ac4  = (tid & 7) * 4;
    const int brow = tid >> 5;
    const int bnc  = (tid & 31) * 4;

    float acc[4][4][4];
#pragma unroll
    for (int mi = 0; mi < 4; mi++)
#pragma unroll
        for (int ni = 0; ni < 4; ni++)
#pragma unroll
            for (int r = 0; r < 4; r++) acc[mi][ni][r] = 0.f;

    float4 apf[4], bpf[4];
#pragma unroll
    for (int i = 0; i < 4; i++)
        apf[i] = *(const float4*)(Ap + (size_t)(arow + 32 * i) * K + ac4);
#pragma unroll
    for (int i = 0; i < 4; i++)
        bpf[i] = *(const float4*)(Bp + (size_t)(brow + 8 * i) * N + bnc);
#pragma unroll
    for (int i = 0; i < 4; i++) {
        *(float4*)(As + (size_t)(arow + 32 * i) * LDA + ac4) =
            make_float4(tf32f(apf[i].x), tf32f(apf[i].y), tf32f(apf[i].z), tf32f(apf[i].w));
        *(float4*)(Bs + (size_t)(brow + 8 * i) * LDB + bnc) =
            make_float4(tf32f(bpf[i].x), tf32f(bpf[i].y), tf32f(bpf[i].z), tf32f(bpf[i].w));
    }
    __syncthreads();

    int buf = 0;
    for (int k0 = 0; k0 < K; k0 += 32) {
        const bool more = (k0 + 32 < K);
        if (more) {
#pragma unroll
            for (int i = 0; i < 4; i++)
                apf[i] = *(const float4*)(Ap + (size_t)(arow + 32 * i) * K + (k0 + 32) + ac4);
#pragma unroll
            for (int i = 0; i < 4; i++)
                bpf[i] = *(const float4*)(Bp + (size_t)(brow + 8 * i + k0 + 32) * N + bnc);
        }

        const float* Ab = As + buf * ASZ;
        const float* Bb = Bs + buf * BSZ;
#pragma unroll
        for (int ks = 0; ks < 4; ks++) {
            const int kb = ks * 8;
            uint32_t af[4][4], bf[4][2];
#pragma unroll
            for (int mi = 0; mi < 4; mi++) {
                const float* ap = Ab + (size_t)(wm + mi * 16 + gid) * LDA + kb + ctid;
                af[mi][0] = __float_as_uint(ap[0]);
                af[mi][1] = __float_as_uint(ap[8 * LDA]);
                af[mi][2] = __float_as_uint(ap[4]);
                af[mi][3] = __float_as_uint(ap[8 * LDA + 4]);
            }
#pragma unroll
            for (int ni = 0; ni < 4; ni++) {
                const float* bp = Bb + (size_t)(kb + ctid) * LDB + wn + ni * 8 + gid;
                bf[ni][0] = __float_as_uint(bp[0]);
                bf[ni][1] = __float_as_uint(bp[4 * LDB]);
            }
#pragma unroll
            for (int mi = 0; mi < 4; mi++)
#pragma unroll
                for (int ni = 0; ni < 4; ni++)
                    mma_tf32(acc[mi][ni], af[mi][0], af[mi][1], af[mi][2], af[mi][3],
                             bf[ni][0], bf[ni][1]);
        }

        if (more) {
            const int nb = buf ^ 1;
            float* An = As + nb * ASZ;
            float* Bn = Bs + nb * BSZ;
#pragma unroll
            for (int i = 0; i < 4; i++) {
                *(float4*)(An + (size_t)(arow + 32 * i) * LDA + ac4) =
                    make_float4(tf32f(apf[i].x), tf32f(apf[i].y), tf32f(apf[i].z), tf32f(apf[i].w));
                *(float4*)(Bn + (size_t)(brow + 8 * i) * LDB + bnc) =
                    make_float4(tf32f(bpf[i].x), tf32f(bpf[i].y), tf32f(bpf[i].z), tf32f(bpf[i].w));
            }
            __syncthreads();
            buf = nb;
        }
    }

#pragma unroll
    for (int mi = 0; mi < 4; mi++) {
#pragma unroll
        for (int ni = 0; ni < 4; ni++) {
            const int r0 = wm + mi * 16 + gid;
            const int cc = wn + ni * 8 + ctid * 2;
            *(float2*)(Cp + (size_t)r0 * N + cc)       = make_float2(acc[mi][ni][0], acc[mi][ni][1]);
            *(float2*)(Cp + (size_t)(r0 + 8) * N + cc) = make_float2(acc[mi][ni][2], acc[mi][ni][3]);
        }
    }
}

__global__ __launch_bounds__(256)
void tgemm(const float* __restrict__ A, const float* __restrict__ Bm,
           float* __restrict__ C, int M, int N, int K) {
    extern __shared__ float smf[];
    float* As = smf;
    float* Bs = smf + 2 * ASZ;
    const int mBase = blockIdx.y * 128;
    const int nBase = blockIdx.x * 128;
    tgemm_body(As, Bs, A + (size_t)mBase * K, Bm + nBase,
               C + (size_t)mBase * N + nBase, N, K, threadIdx.x);
}

__global__ __launch_bounds__(256)
void qkv_tgemm(const float* __restrict__ x,
               const float* __restrict__ wq, const float* __restrict__ wk,
               const float* __restrict__ wv,
               float* __restrict__ pq, float* __restrict__ pk, float* __restrict__ pv) {
    extern __shared__ float smf[];
    float* As = smf;
    float* Bs = smf + 2 * ASZ;
    const int mBase = blockIdx.y * 128;
    const int bx = blockIdx.x;

    const float* W; float* C; int N, nBase;
    if (bx < 16)      { W = wq; C = pq; N = QD_; nBase = bx * 128; }
    else if (bx < 20) { W = wk; C = pk; N = KD_; nBase = (bx - 16) * 128; }
    else              { W = wv; C = pv; N = KD_; nBase = (bx - 20) * 128; }

    tgemm_body(As, Bs, x + (size_t)mBase * D_, W + nBase,
               C + (size_t)mBase * N + nBase, N, D_, threadIdx.x);
}

// ---------------------------------------------------------------------------
// RoPE in place on [M, heads*64]: pair (d, d+32) per thread.
// ---------------------------------------------------------------------------
__global__ void rope_kernel(float* __restrict__ t, const float* __restrict__ cosT,
                            const float* __restrict__ sinT, int heads) {
    const int idx = blockIdx.x * blockDim.x + threadIdx.x;
    const int total = M_ * heads * (HD_ / 2);
    if (idx >= total) return;
    const int d = idx & 31;
    const int h = (idx >> 5) % heads;
    const int m = idx / (heads * 32);
    const int tt = m & (T_ - 1);   // m % T
    const float c = cosT[tt * 32 + d];
    const float s = sinT[tt * 32 + d];
    float* p = t + (size_t)m * heads * HD_ + h * HD_ + d;
    const float q1 = p[0], q2 = p[32];
    p[0]  = fmaf(q1, c, -q2 * s);
    p[32] = fmaf(q2, c,  q1 * s);
}

// ---------------------------------------------------------------------------
// Causal GQA flash attention on tf32 tensor cores.
// Grid: (T/64, H, B). Block: 256 thr = 8 warps as 4(m) x 2(n).
// Warp tile: 16 rows x 32 cols. Q fragments register-resident (pre-scaled).
// K, V in natural [key][d] SMEM layout (pads 68 / 72 -> conflict-free frags).
// Ps overlaid on Qs. Online softmax on S fragments (shfl + SMEM cross-warp).
// ---------------------------------------------------------------------------
#define ALD 68
#define VLD 72
#define ATTN_SMEM ((64 * ALD + 64 * ALD + 64 * VLD + 2 * 64 + 2 * 64 + 64 + 64) * 4)

__global__ __launch_bounds__(256, 2)
void attn_kernel(float* __restrict__ o) {
    extern __shared__ float sm[];
    float* Qs  = sm;                    // [64][ALD], overlaid with Ps
    float* Ps  = sm;
    float* Ks  = sm + 64 * ALD;         // [64][ALD]  (key, d)
    float* Vs  = Ks + 64 * ALD;         // [64][VLD]  (key, d)
    float* pmx = Vs + 64 * VLD;         // [2][64] per-n-warp row max
    float* psm = pmx + 128;             // [2][64] per-n-warp row sum
    float* m_s = psm + 128;             // [64] running max
    float* l_s = m_s + 64;              // [64] running sum

    const int i0  = blockIdx.x * 64;
    const int h   = blockIdx.y;
    const int b   = blockIdx.z;
    const int kvh = h >> 2;             // N_REP = 4
    const int tid  = threadIdx.x;
    const int warp = tid >> 5, lane = tid & 31;
    const int gid = lane >> 2, ctid = lane & 3;
    const int wm = (warp & 3) * 16;     // m-warp row base
    const int nw = warp >> 2;           // 0 or 1
    const int wn = nw * 32;             // n-warp col base
    const int r0 = wm + gid, r1 = r0 + 8;

    // Stage Q tile (scaled by 1/sqrt(64) = 0.125, exact pow2)
#pragma unroll
    for (int it = 0; it < 4; it++) {
        const int idx = tid + it * 256;
        const int row = idx >> 4, d4 = (idx & 15) * 4;
        const float4 qv = *(const float4*)(g_q + (size_t)(b * T_ + i0 + row) * QD_ + h * HD_ + d4);
        *(float4*)&Qs[row * ALD + d4] =
            make_float4(qv.x * 0.125f, qv.y * 0.125f, qv.z * 0.125f, qv.w * 0.125f);
    }
    if (tid < 64) { m_s[tid] = -INFINITY; l_s[tid] = 0.f; }
    __syncthreads();

    // Q fragments -> registers (rna-rounded), 8 k-steps x 4 regs
    uint32_t qf[8][4];
#pragma unroll
    for (int ks = 0; ks < 8; ks++) {
        const float* qp = &Qs[r0 * ALD + ks * 8 + ctid];
        qf[ks][0] = f2tf32(qp[0]);
        qf[ks][1] = f2tf32(qp[8 * ALD]);
        qf[ks][2] = f2tf32(qp[4]);
        qf[ks][3] = f2tf32(qp[8 * ALD + 4]);
    }

    float oacc[4][4];
#pragma unroll
    for (int ni = 0; ni < 4; ni++)
#pragma unroll
        for (int r = 0; r < 4; r++) oacc[ni][r] = 0.f;

    for (int j0 = 0; j0 <= i0; j0 += 64) {
        __syncthreads();   // Ks/Vs/Ps from previous tile fully consumed
        // Stage K, V tiles (natural layout, rna-rounded)
#pragma unroll
        for (int it = 0; it < 4; it++) {
            const int idx = tid + it * 256;
            const int row = idx >> 4, d4 = (idx & 15) * 4;
            const size_t gofs = (size_t)(b * T_ + j0 + row) * KD_ + kvh * HD_ + d4;
            const float4 kv = *(const float4*)(g_k + gofs);
            const float4 vv = *(const float4*)(g_v + gofs);
            *(float4*)&Ks[row * ALD + d4] =
                make_float4(tf32f(kv.x), tf32f(kv.y), tf32f(kv.z), tf32f(kv.w));
            *(float4*)&Vs[row * VLD + d4] =
                make_float4(tf32f(vv.x), tf32f(vv.y), tf32f(vv.z), tf32f(vv.w));
        }
        __syncthreads();

        // S = (Q/8) @ K^T  via mma: B[k=d][n=key] = Ks[key][d]
        float sf[4][4];
#pragma unroll
        for (int ni = 0; ni < 4; ni++)
#pragma unroll
            for (int r = 0; r < 4; r++) sf[ni][r] = 0.f;
#pragma unroll
        for (int ks = 0; ks < 8; ks++) {
#pragma unroll
            for (int ni = 0; ni < 4; ni++) {
                const float* bp = &Ks[(wn + ni * 8 + gid) * ALD + ks * 8 + ctid];
                const uint32_t b0 = __float_as_uint(bp[0]);
                const uint32_t b1 = __float_as_uint(bp[4]);
                mma_tf32(sf[ni], qf[ks][0], qf[ks][1], qf[ks][2], qf[ks][3], b0, b1);
            }
        }

        // Causal mask on diagonal tile
        if (j0 == i0) {
#pragma unroll
            for (int ni = 0; ni < 4; ni++) {
                const int c0 = wn + ni * 8 + 2 * ctid;
                if (c0     > r0) sf[ni][0] = -1e30f;
                if (c0 + 1 > r0) sf[ni][1] = -1e30f;
                if (c0     > r1) sf[ni][2] = -1e30f;
                if (c0 + 1 > r1) sf[ni][3] = -1e30f;
            }
        }

        // Row max: in-warp over ctid lanes, then cross-n-warp via SMEM
        float pm0 = -INFINITY, pm1 = -INFINITY;
#pragma unroll
        for (int ni = 0; ni < 4; ni++) {
            pm0 = fmaxf(pm0, fmaxf(sf[ni][0], sf[ni][1]));
            pm1 = fmaxf(pm1, fmaxf(sf[ni][2], sf[ni][3]));
        }
        pm0 = fmaxf(pm0, __shfl_xor_sync(0xffffffffu, pm0, 1));
        pm0 = fmaxf(pm0, __shfl_xor_sync(0xffffffffu, pm0, 2));
        pm1 = fmaxf(pm1, __shfl_xor_sync(0xffffffffu, pm1, 1));
        pm1 = fmaxf(pm1, __shfl_xor_sync(0xffffffffu, pm1, 2));
        if (ctid == 0) { pmx[nw * 64 + r0] = pm0; pmx[nw * 64 + r1] = pm1; }
        __syncthreads();

        const float mo0 = m_s[r0], mo1 = m_s[r1];
        const float mn0 = fmaxf(mo0, fmaxf(pm0, pmx[(1 - nw) * 64 + r0]));
        const float mn1 = fmaxf(mo1, fmaxf(pm1, pmx[(1 - nw) * 64 + r1]));
        const float al0 = __expf(mo0 - mn0);   // 0 on first tile
        const float al1 = __expf(mo1 - mn1);

        // exp, write P (rna-rounded) to Ps, partial sums (exact fp32)
        float s0 = 0.f, s1 = 0.f;
#pragma unroll
        for (int ni = 0; ni < 4; ni++) {
            const int c0 = wn + ni * 8 + 2 * ctid;
            const float p00 = __expf(sf[ni][0] - mn0);
            const float p01 = __expf(sf[ni][1] - mn0);
            const float p10 = __expf(sf[ni][2] - mn1);
            const float p11 = __expf(sf[ni][3] - mn1);
            s0 += p00 + p01;
            s1 += p10 + p11;
            *(float2*)&Ps[r0 * ALD + c0] = make_float2(tf32f(p00), tf32f(p01));
            *(float2*)&Ps[r1 * ALD + c0] = make_float2(tf32f(p10), tf32f(p11));
        }
        s0 += __shfl_xor_sync(0xffffffffu, s0, 1);
        s0 += __shfl_xor_sync(0xffffffffu, s0, 2);
        s1 += __shfl_xor_sync(0xffffffffu, s1, 1);
        s1 += __shfl_xor_sync(0xffffffffu, s1, 2);
        if (ctid == 0) { psm[nw * 64 + r0] = s0; psm[nw * 64 + r1] = s1; }

        // Rescale O accumulators
#pragma unroll
        for (int ni = 0; ni < 4; ni++) {
            oacc[ni][0] *= al0; oacc[ni][1] *= al0;
            oacc[ni][2] *= al1; oacc[ni][3] *= al1;
        }
        __syncthreads();

        // Single writer per row updates running stats
        if (nw == 0 && ctid == 0) {
            l_s[r0] = l_s[r0] * al0 + psm[r0] + psm[64 + r0];
            l_s[r1] = l_s[r1] * al1 + psm[r1] + psm[64 + r1];
            m_s[r0] = mn0; m_s[r1] = mn1;
        }

        // O += P @ V via mma: B[k=key][n=d] = Vs[key][d]
#pragma unroll
        for (int ks = 0; ks < 8; ks++) {
            const float* ap = &Ps[r0 * ALD + ks * 8 + ctid];
            const uint32_t a0 = __float_as_uint(ap[0]);
            const uint32_t a1 = __float_as_uint(ap[8 * ALD]);
            const uint32_t a2 = __float_as_uint(ap[4]);
            const uint32_t a3 = __float_as_uint(ap[8 * ALD + 4]);
#pragma unroll
            for (int ni = 0; ni < 4; ni++) {
                const float* bp = &Vs[(ks * 8 + ctid) * VLD + wn + ni * 8 + gid];
                const uint32_t b0 = __float_as_uint(bp[0]);
                const uint32_t b1 = __float_as_uint(bp[4 * VLD]);
                mma_tf32(oacc[ni], a0, a1, a2, a3, b0, b1);
            }
        }
    }

    __syncthreads();
    const float li0 = 1.0f / l_s[r0];
    const float li1 = 1.0f / l_s[r1];
#pragma unroll
    for (int ni = 0; ni < 4; ni++) {
        const int c0 = wn + ni * 8 + 2 * ctid;
        float* op0 = o + (size_t)(b * T_ + i0 + r0) * QD_ + h * HD_ + c0;
        float* op1 = o + (size_t)(b * T_ + i0 + r1) * QD_ + h * HD_ + c0;
        *(float2*)op0 = make_float2(oacc[ni][0] * li0, oacc[ni][1] * li0);
        *(float2*)op1 = make_float2(oacc[ni][2] * li1, oacc[ni][3] * li1);
    }
}

// ---------------------------------------------------------------------------
// Launch
// ---------------------------------------------------------------------------
extern "C" void kernel_launch(void* const* d_in, const int* in_sizes, int n_in,
                              void* d_out, int out_size) {
    const float* x    = (const float*)d_in[0];
    const float* cosT = (const float*)d_in[1];
    const float* sinT = (const float*)d_in[2];
    const float* wq   = (const float*)d_in[3];
    const float* wk   = (const float*)d_in[4];
    const float* wv   = (const float*)d_in[5];
    const float* wo   = (const float*)d_in[6];
    float* out        = (float*)d_out;

    float *pq, *pk, *pv, *pa;
    cudaGetSymbolAddress((void**)&pq, g_q);
    cudaGetSymbolAddress((void**)&pk, g_k);
    cudaGetSymbolAddress((void**)&pv, g_v);
    cudaGetSymbolAddress((void**)&pa, g_att);

    cudaFuncSetAttribute(qkv_tgemm, cudaFuncAttributeMaxDynamicSharedMemorySize, TG_SMEM_BYTES);
    cudaFuncSetAttribute(tgemm, cudaFuncAttributeMaxDynamicSharedMemorySize, TG_SMEM_BYTES);
    cudaFuncSetAttribute(attn_kernel, cudaFuncAttributeMaxDynamicSharedMemorySize, ATTN_SMEM);

    // Fused QKV projections (tf32 tensor cores)
    qkv_tgemm<<<dim3(24, M_ / 128), 256, TG_SMEM_BYTES>>>(x, wq, wk, wv, pq, pk, pv);

    // RoPE on Q and K
    {
        const int tq = M_ * H_ * (HD_ / 2);
        rope_kernel<<<(tq + 255) / 256, 256>>>(pq, cosT, sinT, H_);
        const int tk = M_ * KVH_ * (HD_ / 2);
        rope_kernel<<<(tk + 255) / 256, 256>>>(pk, cosT, sinT, KVH_);
    }

    // Attention (tf32 tensor cores)
    attn_kernel<<<dim3(T_ / 64, H_, B_), 256, ATTN_SMEM>>>(pa);

    // Output projection (tf32 tensor cores)
    tgemm<<<dim3(D_ / 128, M_ / 128), 256, TG_SMEM_BYTES>>>(pa, wo, out, M_, D_, D_);
}